// round 2
// baseline (speedup 1.0000x reference)
#include <cuda_runtime.h>
#include <math.h>

#define B_ 16
#define N_ 512
#define H_ 8
#define E_ 128
#define BH_ (B_*H_)
#define NEGV (-1000000000.0f)

// Intermediates in device globals (no runtime allocation allowed).
// Layout: [B, H, N, E] row-major, i.e. [(b*H+h)*N + n]*E + e
__device__ float g_q[BH_*N_*E_];
__device__ float g_k[BH_*N_*E_];
__device__ float g_v[BH_*N_*E_];
__device__ float g_y[BH_*N_*E_];

// ---------------------------------------------------------------------------
// Kernel 1: fused QKV projection.  C[8192,1024] = X[8192,128] @ W^T + b
// blockIdx.z selects q/k/v.  64x64 tile, 256 threads, 4x4 micro-tile.
// ---------------------------------------------------------------------------
__global__ __launch_bounds__(256) void qkv_kernel(
    const float* __restrict__ x,
    const float* __restrict__ Wq, const float* __restrict__ bq,
    const float* __restrict__ Wk, const float* __restrict__ bk,
    const float* __restrict__ Wv, const float* __restrict__ bv)
{
    const int which = blockIdx.z;
    const float* __restrict__ W    = (which == 0) ? Wq : (which == 1) ? Wk : Wv;
    const float* __restrict__ bias = (which == 0) ? bq : (which == 1) ? bk : bv;
    float* __restrict__ out        = (which == 0) ? g_q : (which == 1) ? g_k : g_v;

    __shared__ float xs[64][68];   // [e][row], pad 68 for float4-aligned, conflict-free reads
    __shared__ float ws[64][68];   // [e][col]

    const int tid  = threadIdx.x;
    const int ty   = tid >> 4;          // 0..15 -> 4 rows each
    const int tx   = tid & 15;          // 0..15 -> 4 cols each
    const int row0 = blockIdx.x << 6;   // 128 blocks over 8192 rows
    const int col0 = blockIdx.y << 6;   // 16 blocks over 1024 cols

    float acc[4][4] = {};

    for (int e0 = 0; e0 < 128; e0 += 64) {
        #pragma unroll
        for (int i = 0; i < 16; i++) {
            int idx = tid + (i << 8);
            int r = idx >> 6, e = idx & 63;
            xs[e][r] = x[(row0 + r) * E_ + e0 + e];
        }
        #pragma unroll
        for (int i = 0; i < 16; i++) {
            int idx = tid + (i << 8);
            int c = idx >> 6, e = idx & 63;
            ws[e][c] = W[(col0 + c) * E_ + e0 + e];
        }
        __syncthreads();
        #pragma unroll 8
        for (int e = 0; e < 64; e++) {
            float4 av = *(const float4*)&xs[e][ty << 2];
            float4 wv = *(const float4*)&ws[e][tx << 2];
            float a[4] = {av.x, av.y, av.z, av.w};
            float w[4] = {wv.x, wv.y, wv.z, wv.w};
            #pragma unroll
            for (int i = 0; i < 4; i++)
                #pragma unroll
                for (int j = 0; j < 4; j++)
                    acc[i][j] += a[i] * w[j];
        }
        __syncthreads();
    }

    const int col = col0 + (tx << 2);
    const int h = col >> 7, e = col & 127;      // col within 1024 = h*128+e
    float4 bv4 = *(const float4*)&bias[col];
    #pragma unroll
    for (int i = 0; i < 4; i++) {
        int row = row0 + (ty << 2) + i;
        int b = row >> 9, n = row & 511;
        float4 o = make_float4(acc[i][0] + bv4.x, acc[i][1] + bv4.y,
                               acc[i][2] + bv4.z, acc[i][3] + bv4.w);
        *(float4*)&out[((size_t)((b * H_ + h) * N_ + n) << 7) + e] = o;
    }
}

// ---------------------------------------------------------------------------
// Kernel 2: attention for one (b,h) and 32 queries per block.
// Full 512-key score row in smem -> exact softmax -> P@V.
// Dynamic smem layout (floats):
//   qs  [128][36]   (Q transposed, e-major)        4608
//   kvs [128][132]  (K transposed / V natural)    16896
//   ss  [32][520]   (scores/probs)                16640
//   mk  [512]       (key mask row)                  512
// total = 38656 floats = 154624 bytes
// ---------------------------------------------------------------------------
#define SMEM_ATTN_BYTES 154624

__global__ __launch_bounds__(256) void attn_kernel(
    const float* __restrict__ dist, const float* __restrict__ mask)
{
    extern __shared__ float sm[];
    float* qs  = sm;                    // stride 36
    float* kvs = sm + 128 * 36;        // stride 132
    float* ss  = kvs + 128 * 132;      // stride 520
    float* mk  = ss + 32 * 520;

    const int tid = threadIdx.x;
    const int bh  = blockIdx.y;        // 0..127
    const int b   = bh >> 3;
    const int q0  = blockIdx.x << 5;   // 16 q-tiles of 32

    const float* __restrict__ Q = g_q + (size_t)bh * N_ * E_;
    const float* __restrict__ K = g_k + (size_t)bh * N_ * E_;
    const float* __restrict__ V = g_v + (size_t)bh * N_ * E_;

    // key mask row
    for (int i = tid; i < 512; i += 256) mk[i] = mask[b * 512 + i];

    // load Q tile transposed: 32 rows x 128 e
    #pragma unroll
    for (int i = 0; i < 16; i++) {
        int idx = tid + (i << 8);
        int r = idx >> 7, e = idx & 127;
        qs[e * 36 + r] = Q[(q0 + r) * E_ + e];
    }
    __syncthreads();

    const int ty = tid >> 5;    // 0..7 -> 4 query rows each (32 rows)
    const int tx = tid & 31;    // 0..31 -> 4 key cols each (128 cols)
    const float scale = 0.0883883476483184f;  // 128^-0.5

    // ---- Phase 1: S = scale*(Q K^T) + dist, key-masked, into ss ----
    for (int kt = 0; kt < 4; kt++) {
        #pragma unroll
        for (int i = 0; i < 64; i++) {
            int idx = tid + (i << 8);
            int r = idx >> 7, e = idx & 127;
            kvs[e * 132 + r] = K[(kt * 128 + r) * E_ + e];
        }
        __syncthreads();

        float acc[4][4] = {};
        #pragma unroll 8
        for (int e = 0; e < 128; e++) {
            float4 qv = *(const float4*)&qs[e * 36 + (ty << 2)];
            float4 kv = *(const float4*)&kvs[e * 132 + (tx << 2)];
            float a[4] = {qv.x, qv.y, qv.z, qv.w};
            float c[4] = {kv.x, kv.y, kv.z, kv.w};
            #pragma unroll
            for (int i = 0; i < 4; i++)
                #pragma unroll
                for (int j = 0; j < 4; j++)
                    acc[i][j] += a[i] * c[j];
        }

        const int kbase = kt * 128 + (tx << 2);
        float m0 = mk[kbase + 0], m1 = mk[kbase + 1], m2 = mk[kbase + 2], m3 = mk[kbase + 3];
        #pragma unroll
        for (int i = 0; i < 4; i++) {
            int qg = q0 + (ty << 2) + i;
            float4 dv = *(const float4*)&dist[((size_t)b * N_ + qg) * N_ + kbase];
            float4 s;
            s.x = (m0 != 0.f) ? acc[i][0] * scale + dv.x : NEGV;
            s.y = (m1 != 0.f) ? acc[i][1] * scale + dv.y : NEGV;
            s.z = (m2 != 0.f) ? acc[i][2] * scale + dv.z : NEGV;
            s.w = (m3 != 0.f) ? acc[i][3] * scale + dv.w : NEGV;
            *(float4*)&ss[((ty << 2) + i) * 520 + kbase] = s;
        }
        __syncthreads();
    }

    // ---- Phase 2: row softmax (8 warps x 4 rows) ----
    {
        const int warp = tid >> 5, lane = tid & 31;
        #pragma unroll
        for (int rr = 0; rr < 4; rr++) {
            int r = (warp << 2) + rr;
            float m = NEGV;
            for (int j = lane; j < 512; j += 32) m = fmaxf(m, ss[r * 520 + j]);
            #pragma unroll
            for (int o = 16; o; o >>= 1) m = fmaxf(m, __shfl_xor_sync(0xffffffff, m, o));
            float l = 0.f;
            for (int j = lane; j < 512; j += 32) {
                float p = __expf(ss[r * 520 + j] - m);
                ss[r * 520 + j] = p;
                l += p;
            }
            #pragma unroll
            for (int o = 16; o; o >>= 1) l += __shfl_xor_sync(0xffffffff, l, o);
            float inv = 1.f / l;
            for (int j = lane; j < 512; j += 32) ss[r * 520 + j] *= inv;
        }
    }
    __syncthreads();

    // ---- Phase 3: Y = P @ V ----
    float acc2[4][4] = {};
    for (int kt = 0; kt < 4; kt++) {
        // load V tile natural layout [key][e], float4
        #pragma unroll
        for (int i = 0; i < 16; i++) {
            int idx = tid + (i << 8);        // 4096 float4 slots
            int key = idx >> 5, e4 = idx & 31;
            float4 vv = *(const float4*)&V[(kt * 128 + key) * E_ + (e4 << 2)];
            *(float4*)&kvs[key * 132 + (e4 << 2)] = vv;
        }
        __syncthreads();

        #pragma unroll 4
        for (int kk = 0; kk < 128; kk++) {
            int c = kt * 128 + kk;
            float p0 = ss[((ty << 2) + 0) * 520 + c];
            float p1 = ss[((ty << 2) + 1) * 520 + c];
            float p2 = ss[((ty << 2) + 2) * 520 + c];
            float p3 = ss[((ty << 2) + 3) * 520 + c];
            float4 vv = *(const float4*)&kvs[kk * 132 + (tx << 2)];
            acc2[0][0] += p0 * vv.x; acc2[0][1] += p0 * vv.y; acc2[0][2] += p0 * vv.z; acc2[0][3] += p0 * vv.w;
            acc2[1][0] += p1 * vv.x; acc2[1][1] += p1 * vv.y; acc2[1][2] += p1 * vv.z; acc2[1][3] += p1 * vv.w;
            acc2[2][0] += p2 * vv.x; acc2[2][1] += p2 * vv.y; acc2[2][2] += p2 * vv.z; acc2[2][3] += p2 * vv.w;
            acc2[3][0] += p3 * vv.x; acc2[3][1] += p3 * vv.y; acc2[3][2] += p3 * vv.z; acc2[3][3] += p3 * vv.w;
        }
        __syncthreads();
    }

    float* __restrict__ Y = g_y + (size_t)bh * N_ * E_;
    #pragma unroll
    for (int i = 0; i < 4; i++) {
        int qg = q0 + (ty << 2) + i;
        *(float4*)&Y[qg * E_ + (tx << 2)] =
            make_float4(acc2[i][0], acc2[i][1], acc2[i][2], acc2[i][3]);
    }
}

// ---------------------------------------------------------------------------
// Kernel 3: out[8192,128] = Y[8192,1024] @ Wo^T + bo, then * mask[b,n]
// 64x64 tiles, K chunks of 64 (each chunk within one head).
// ---------------------------------------------------------------------------
__global__ __launch_bounds__(256) void oproj_kernel(
    const float* __restrict__ Wo, const float* __restrict__ bo,
    const float* __restrict__ mask, float* __restrict__ out)
{
    __shared__ float as_[64][68];
    __shared__ float ws_[64][68];

    const int tid  = threadIdx.x;
    const int ty   = tid >> 4;
    const int tx   = tid & 15;
    const int row0 = blockIdx.x << 6;   // 128 blocks over 8192 rows
    const int col0 = blockIdx.y << 6;   // 2 blocks over 128 cols

    float acc[4][4] = {};

    for (int k0 = 0; k0 < 1024; k0 += 64) {
        const int h = k0 >> 7;
        const int eoff = k0 & 127;
        #pragma unroll
        for (int i = 0; i < 16; i++) {
            int idx = tid + (i << 8);
            int r = idx >> 6, kk = idx & 63;
            int row = row0 + r;
            int b = row >> 9, n = row & 511;
            as_[kk][r] = g_y[((size_t)((b * H_ + h) * N_ + n) << 7) + eoff + kk];
        }
        #pragma unroll
        for (int i = 0; i < 16; i++) {
            int idx = tid + (i << 8);
            int c = idx >> 6, kk = idx & 63;
            ws_[kk][c] = Wo[(col0 + c) * 1024 + k0 + kk];
        }
        __syncthreads();
        #pragma unroll 8
        for (int kk = 0; kk < 64; kk++) {
            float4 av = *(const float4*)&as_[kk][ty << 2];
            float4 wv = *(const float4*)&ws_[kk][tx << 2];
            float a[4] = {av.x, av.y, av.z, av.w};
            float w[4] = {wv.x, wv.y, wv.z, wv.w};
            #pragma unroll
            for (int i = 0; i < 4; i++)
                #pragma unroll
                for (int j = 0; j < 4; j++)
                    acc[i][j] += a[i] * w[j];
        }
        __syncthreads();
    }

    float4 bv4 = *(const float4*)&bo[col0 + (tx << 2)];
    #pragma unroll
    for (int i = 0; i < 4; i++) {
        int row = row0 + (ty << 2) + i;
        int b = row >> 9, n = row & 511;
        float mv = mask[b * 512 + n];
        float4 o = make_float4((acc[i][0] + bv4.x) * mv, (acc[i][1] + bv4.y) * mv,
                               (acc[i][2] + bv4.z) * mv, (acc[i][3] + bv4.w) * mv);
        *(float4*)&out[(size_t)row * E_ + col0 + (tx << 2)] = o;
    }
}

// ---------------------------------------------------------------------------
extern "C" void kernel_launch(void* const* d_in, const int* in_sizes, int n_in,
                              void* d_out, int out_size)
{
    const float* x    = (const float*)d_in[0];
    const float* dist = (const float*)d_in[1];
    const float* mask = (const float*)d_in[2];
    const float* Wq   = (const float*)d_in[3];
    const float* bq   = (const float*)d_in[4];
    const float* Wk   = (const float*)d_in[5];
    const float* bk   = (const float*)d_in[6];
    const float* Wv   = (const float*)d_in[7];
    const float* bv   = (const float*)d_in[8];
    const float* Wo   = (const float*)d_in[9];
    const float* bo   = (const float*)d_in[10];
    float* out = (float*)d_out;

    cudaFuncSetAttribute(attn_kernel,
                         cudaFuncAttributeMaxDynamicSharedMemorySize,
                         SMEM_ATTN_BYTES);

    qkv_kernel<<<dim3(128, 16, 3), 256>>>(x, Wq, bq, Wk, bk, Wv, bv);
    attn_kernel<<<dim3(16, 128), 256, SMEM_ATTN_BYTES>>>(dist, mask);
    oproj_kernel<<<dim3(128, 2), 256>>>(Wo, bo, mask, out);
}

// round 4
// speedup vs baseline: 1.8606x; 1.8606x over previous
#include <cuda_runtime.h>
#include <cuda_bf16.h>
#include <math.h>

#define B_ 16
#define N_ 512
#define H_ 8
#define E_ 128
#define BH_ (B_*H_)
#define NEGV (-1000000000.0f)
#define SCALE_ 0.08838834764831845f

// Intermediates in device globals (no runtime allocation allowed).
__device__ float g_q[BH_*N_*E_];
__device__ float g_k[BH_*N_*E_];
__device__ float g_v[BH_*N_*E_];
__device__ float g_y[BH_*N_*E_];

// ---------------------------------------------------------------------------
// Kernel 1: fused QKV projection (fp32 SIMT, proven at ~88% of FFMA roofline)
// ---------------------------------------------------------------------------
__global__ __launch_bounds__(256) void qkv_kernel(
    const float* __restrict__ x,
    const float* __restrict__ Wq, const float* __restrict__ bq,
    const float* __restrict__ Wk, const float* __restrict__ bk,
    const float* __restrict__ Wv, const float* __restrict__ bv)
{
    const int which = blockIdx.z;
    const float* __restrict__ W    = (which == 0) ? Wq : (which == 1) ? Wk : Wv;
    const float* __restrict__ bias = (which == 0) ? bq : (which == 1) ? bk : bv;
    float* __restrict__ out        = (which == 0) ? g_q : (which == 1) ? g_k : g_v;

    __shared__ float xs[64][68];
    __shared__ float ws[64][68];

    const int tid  = threadIdx.x;
    const int ty   = tid >> 4;
    const int tx   = tid & 15;
    const int row0 = blockIdx.x << 6;
    const int col0 = blockIdx.y << 6;

    float acc[4][4] = {};

    for (int e0 = 0; e0 < 128; e0 += 64) {
        #pragma unroll
        for (int i = 0; i < 16; i++) {
            int idx = tid + (i << 8);
            int r = idx >> 6, e = idx & 63;
            xs[e][r] = x[(row0 + r) * E_ + e0 + e];
        }
        #pragma unroll
        for (int i = 0; i < 16; i++) {
            int idx = tid + (i << 8);
            int c = idx >> 6, e = idx & 63;
            ws[e][c] = W[(col0 + c) * E_ + e0 + e];
        }
        __syncthreads();
        #pragma unroll 8
        for (int e = 0; e < 64; e++) {
            float4 av = *(const float4*)&xs[e][ty << 2];
            float4 wv = *(const float4*)&ws[e][tx << 2];
            float a[4] = {av.x, av.y, av.z, av.w};
            float w[4] = {wv.x, wv.y, wv.z, wv.w};
            #pragma unroll
            for (int i = 0; i < 4; i++)
                #pragma unroll
                for (int j = 0; j < 4; j++)
                    acc[i][j] += a[i] * w[j];
        }
        __syncthreads();
    }

    const int col = col0 + (tx << 2);
    const int h = col >> 7, e = col & 127;
    float4 bv4 = *(const float4*)&bias[col];
    #pragma unroll
    for (int i = 0; i < 4; i++) {
        int row = row0 + (ty << 2) + i;
        int b = row >> 9, n = row & 511;
        float4 o = make_float4(acc[i][0] + bv4.x, acc[i][1] + bv4.y,
                               acc[i][2] + bv4.z, acc[i][3] + bv4.w);
        *(float4*)&out[((size_t)((b * H_ + h) * N_ + n) << 7) + e] = o;
    }
}

// ---------------------------------------------------------------------------
// mma.sync / ldmatrix helpers (base PTX, sm_80+, works on target sm_103)
// ---------------------------------------------------------------------------
__device__ __forceinline__ unsigned smem_u32(const void* p) {
    unsigned r;
    asm("{ .reg .u64 t; cvta.to.shared.u64 t, %1; cvt.u32.u64 %0, t; }" : "=r"(r) : "l"(p));
    return r;
}
__device__ __forceinline__ void ldsm4(unsigned r[4], unsigned addr) {
    asm volatile("ldmatrix.sync.aligned.m8n8.x4.shared.b16 {%0,%1,%2,%3}, [%4];"
        : "=r"(r[0]), "=r"(r[1]), "=r"(r[2]), "=r"(r[3]) : "r"(addr));
}
__device__ __forceinline__ void ldsm4t(unsigned r[4], unsigned addr) {
    asm volatile("ldmatrix.sync.aligned.m8n8.x4.trans.shared.b16 {%0,%1,%2,%3}, [%4];"
        : "=r"(r[0]), "=r"(r[1]), "=r"(r[2]), "=r"(r[3]) : "r"(addr));
}
__device__ __forceinline__ void mma16816(float c[4], const unsigned a[4],
                                         unsigned b0, unsigned b1) {
    asm volatile("mma.sync.aligned.m16n8k16.row.col.f32.bf16.bf16.f32 "
        "{%0,%1,%2,%3}, {%4,%5,%6,%7}, {%8,%9}, {%0,%1,%2,%3};"
        : "+f"(c[0]), "+f"(c[1]), "+f"(c[2]), "+f"(c[3])
        : "r"(a[0]), "r"(a[1]), "r"(a[2]), "r"(a[3]), "r"(b0), "r"(b1));
}

// smem layout (bytes). Operand tiles are 128 rows x 136 bf16 (272B row stride).
#define QH_OFF   0
#define QL_OFF   34816
#define KH_OFF   69632     /* shared K/V chunk buffer */
#define KL_OFF   104448
#define PH_OFF   139264
#define PL_OFF   174080
#define MK_OFF   208896    /* 512 f32 */
#define MS_OFF   210944    /* 128 f32 running max  */
#define LS_OFF   211456    /* 128 f32 running sum  */
#define WMAX_OFF 211968    /* 2 x 128 f32 */
#define WSUM_OFF 212992    /* 2 x 128 f32 */
#define SMEM_ATTN 214016

// load 128x128 fp32 tile from global, scale, split to bf16 hi/lo in smem
__device__ __forceinline__ void load_split_tile(const float* __restrict__ src,
        char* smc, int offH, int offL, float scale, int tid)
{
    #pragma unroll
    for (int i = 0; i < 16; i++) {
        int idx = tid + (i << 8);
        int r = idx >> 5, c4 = idx & 31;
        float4 v = *(const float4*)(src + (size_t)r * E_ + c4 * 4);
        float x0 = v.x * scale, x1 = v.y * scale, x2 = v.z * scale, x3 = v.w * scale;
        __nv_bfloat162 h01 = __floats2bfloat162_rn(x0, x1);
        __nv_bfloat162 h23 = __floats2bfloat162_rn(x2, x3);
        __nv_bfloat162 l01 = __floats2bfloat162_rn(
            x0 - __bfloat162float(__low2bfloat16(h01)),
            x1 - __bfloat162float(__high2bfloat16(h01)));
        __nv_bfloat162 l23 = __floats2bfloat162_rn(
            x2 - __bfloat162float(__low2bfloat16(h23)),
            x3 - __bfloat162float(__high2bfloat16(h23)));
        uint2 uh = make_uint2(*(unsigned*)&h01, *(unsigned*)&h23);
        uint2 ul = make_uint2(*(unsigned*)&l01, *(unsigned*)&l23);
        *(uint2*)(smc + offH + r * 272 + c4 * 8) = uh;
        *(uint2*)(smc + offL + r * 272 + c4 * 8) = ul;
    }
}

// ---------------------------------------------------------------------------
// Kernel 2: flash-style attention on mma.sync (split-bf16, 3-term).
// 1 CTA per (b,h,128-query tile). 8 warps.
//   S phase: warp (wm,wn) = (wid>>1, wid&1): 32q x 64k per 128-key chunk.
//   PV phase: warp wid: 16q x 128e.
// ---------------------------------------------------------------------------
__global__ __launch_bounds__(256, 1) void attn_mma_kernel(
    const float* __restrict__ dist, const float* __restrict__ mask)
{
    extern __shared__ char smc[];
    const unsigned sb = smem_u32(smc);
    float* mk   = (float*)(smc + MK_OFF);
    float* m_s  = (float*)(smc + MS_OFF);
    float* l_s  = (float*)(smc + LS_OFF);
    float* wmax = (float*)(smc + WMAX_OFF);
    float* wsum = (float*)(smc + WSUM_OFF);

    const int tid  = threadIdx.x;
    const int lane = tid & 31;
    const int wid  = tid >> 5;
    const int wm   = wid >> 1;
    const int wn   = wid & 1;
    const int gid  = lane >> 2;
    const int tig  = lane & 3;

    const int q0 = blockIdx.x << 7;
    const int bh = blockIdx.y;
    const int b  = bh >> 3;

    for (int i = tid; i < 512; i += 256) mk[i] = mask[b * 512 + i];
    if (tid < 128) { m_s[tid] = -3.0e38f; l_s[tid] = 0.f; }

    // Q (scaled) -> smem hi/lo
    load_split_tile(g_q + ((size_t)bh * N_ + q0) * E_, smc, QH_OFF, QL_OFF, SCALE_, tid);

    float o[16][4] = {};

    // ldmatrix address components (bytes)
    const int a_row = (lane & 15);
    const int a_col = ((lane >> 4) << 3);
    const int b_key = (lane & 7) + ((lane >> 4) << 3);   // S-gemm B (non-trans)
    const int b_ecol = (((lane >> 3) & 1) << 3);
    const int v_key = (lane & 7) + (((lane >> 3) & 1) << 3);  // PV B (trans)
    const int v_ecol = ((lane >> 4) << 3);

    for (int kt = 0; kt < 4; kt++) {
        // ---- load K chunk ----
        load_split_tile(g_k + ((size_t)bh * N_ + kt * 128) * E_, smc, KH_OFF, KL_OFF, 1.0f, tid);
        __syncthreads();

        // ---- S = Q K^T (3-term split) ----
        float acc[2][8][4] = {};
        #pragma unroll
        for (int k = 0; k < 8; k++) {
            unsigned ah[2][4], al[2][4];
            #pragma unroll
            for (int mf = 0; mf < 2; mf++) {
                unsigned ao = (unsigned)((wm * 32 + mf * 16 + a_row) * 272 + (k * 16 + a_col) * 2);
                ldsm4(ah[mf], sb + QH_OFF + ao);
                ldsm4(al[mf], sb + QL_OFF + ao);
            }
            #pragma unroll
            for (int ng = 0; ng < 4; ng++) {
                unsigned bo = (unsigned)((wn * 64 + ng * 16 + b_key) * 272 + (k * 16 + b_ecol) * 2);
                unsigned bh4[4], bl4[4];
                ldsm4(bh4, sb + KH_OFF + bo);
                ldsm4(bl4, sb + KL_OFF + bo);
                #pragma unroll
                for (int mf = 0; mf < 2; mf++) {
                    mma16816(acc[mf][2*ng],   ah[mf], bh4[0], bh4[1]);
                    mma16816(acc[mf][2*ng],   ah[mf], bl4[0], bl4[1]);
                    mma16816(acc[mf][2*ng],   al[mf], bh4[0], bh4[1]);
                    mma16816(acc[mf][2*ng+1], ah[mf], bh4[2], bh4[3]);
                    mma16816(acc[mf][2*ng+1], ah[mf], bl4[2], bl4[3]);
                    mma16816(acc[mf][2*ng+1], al[mf], bh4[2], bh4[3]);
                }
            }
        }

        // ---- epilogue: + dist, key mask, row max ----
        float mx[2][2] = {{-3.0e38f, -3.0e38f}, {-3.0e38f, -3.0e38f}};
        #pragma unroll
        for (int mf = 0; mf < 2; mf++) {
            const int lr0 = wm * 32 + mf * 16 + gid;
            #pragma unroll
            for (int nf = 0; nf < 8; nf++) {
                const int cb = wn * 64 + nf * 8 + 2 * tig;
                const int gcol = kt * 128 + cb;
                const float* dp = dist + ((size_t)b * N_ + q0 + lr0) * N_ + gcol;
                float2 d0 = *(const float2*)dp;
                float2 d1 = *(const float2*)(dp + 8 * N_);
                const bool k0 = (mk[gcol] != 0.f), k1 = (mk[gcol + 1] != 0.f);
                float s0 = k0 ? acc[mf][nf][0] + d0.x : NEGV;
                float s1 = k1 ? acc[mf][nf][1] + d0.y : NEGV;
                float s2 = k0 ? acc[mf][nf][2] + d1.x : NEGV;
                float s3 = k1 ? acc[mf][nf][3] + d1.y : NEGV;
                acc[mf][nf][0] = s0; acc[mf][nf][1] = s1;
                acc[mf][nf][2] = s2; acc[mf][nf][3] = s3;
                mx[mf][0] = fmaxf(mx[mf][0], fmaxf(s0, s1));
                mx[mf][1] = fmaxf(mx[mf][1], fmaxf(s2, s3));
            }
        }
        #pragma unroll
        for (int mf = 0; mf < 2; mf++)
            #pragma unroll
            for (int hh = 0; hh < 2; hh++) {
                float m = mx[mf][hh];
                m = fmaxf(m, __shfl_xor_sync(0xffffffffu, m, 1));
                m = fmaxf(m, __shfl_xor_sync(0xffffffffu, m, 2));
                mx[mf][hh] = m;
            }
        if (tig == 0) {
            #pragma unroll
            for (int mf = 0; mf < 2; mf++)
                #pragma unroll
                for (int hh = 0; hh < 2; hh++)
                    wmax[wn * 128 + wm * 32 + mf * 16 + gid + 8 * hh] = mx[mf][hh];
        }
        __syncthreads();   // wmax ready; K smem dead

        // ---- load V chunk (overwrites K buffer) ----
        load_split_tile(g_v + ((size_t)bh * N_ + kt * 128) * E_, smc, KH_OFF, KL_OFF, 1.0f, tid);

        // ---- online stats + P = exp(S - m_new), split to bf16 hi/lo ----
        float mnew[2][2], alph[2][2], rs[2][2] = {};
        #pragma unroll
        for (int mf = 0; mf < 2; mf++)
            #pragma unroll
            for (int hh = 0; hh < 2; hh++) {
                const int r = wm * 32 + mf * 16 + gid + 8 * hh;
                const float mo = m_s[r];
                const float mn = fmaxf(fmaxf(wmax[r], wmax[128 + r]), mo);
                mnew[mf][hh] = mn;
                alph[mf][hh] = __expf(mo - mn);
            }
        #pragma unroll
        for (int mf = 0; mf < 2; mf++) {
            const int lr0 = wm * 32 + mf * 16 + gid;
            #pragma unroll
            for (int nf = 0; nf < 8; nf++) {
                const int cb = wn * 64 + nf * 8 + 2 * tig;
                float p0 = __expf(acc[mf][nf][0] - mnew[mf][0]);
                float p1 = __expf(acc[mf][nf][1] - mnew[mf][0]);
                float p2 = __expf(acc[mf][nf][2] - mnew[mf][1]);
                float p3 = __expf(acc[mf][nf][3] - mnew[mf][1]);
                rs[mf][0] += p0 + p1;
                rs[mf][1] += p2 + p3;
                __nv_bfloat162 hA = __floats2bfloat162_rn(p0, p1);
                __nv_bfloat162 lA = __floats2bfloat162_rn(
                    p0 - __bfloat162float(__low2bfloat16(hA)),
                    p1 - __bfloat162float(__high2bfloat16(hA)));
                __nv_bfloat162 hB = __floats2bfloat162_rn(p2, p3);
                __nv_bfloat162 lB = __floats2bfloat162_rn(
                    p2 - __bfloat162float(__low2bfloat16(hB)),
                    p3 - __bfloat162float(__high2bfloat16(hB)));
                *(unsigned*)(smc + PH_OFF + lr0 * 272 + cb * 2)       = *(unsigned*)&hA;
                *(unsigned*)(smc + PL_OFF + lr0 * 272 + cb * 2)       = *(unsigned*)&lA;
                *(unsigned*)(smc + PH_OFF + (lr0 + 8) * 272 + cb * 2) = *(unsigned*)&hB;
                *(unsigned*)(smc + PL_OFF + (lr0 + 8) * 272 + cb * 2) = *(unsigned*)&lB;
            }
        }
        #pragma unroll
        for (int mf = 0; mf < 2; mf++)
            #pragma unroll
            for (int hh = 0; hh < 2; hh++) {
                float s = rs[mf][hh];
                s += __shfl_xor_sync(0xffffffffu, s, 1);
                s += __shfl_xor_sync(0xffffffffu, s, 2);
                rs[mf][hh] = s;
            }
        if (tig == 0) {
            #pragma unroll
            for (int mf = 0; mf < 2; mf++)
                #pragma unroll
                for (int hh = 0; hh < 2; hh++)
                    wsum[wn * 128 + wm * 32 + mf * 16 + gid + 8 * hh] = rs[mf][hh];
        }
        // ---- rescale O accumulators (O mapping: warp wid owns rows 16*wid..) ----
        {
            const int ro0 = wid * 16 + gid;
            const float mo0 = m_s[ro0];
            const float a0 = __expf(mo0 - fmaxf(fmaxf(wmax[ro0], wmax[128 + ro0]), mo0));
            const int ro1 = ro0 + 8;
            const float mo1 = m_s[ro1];
            const float a1 = __expf(mo1 - fmaxf(fmaxf(wmax[ro1], wmax[128 + ro1]), mo1));
            #pragma unroll
            for (int nf = 0; nf < 16; nf++) {
                o[nf][0] *= a0; o[nf][1] *= a0;
                o[nf][2] *= a1; o[nf][3] *= a1;
            }
        }
        __syncthreads();   // P, V, wsum ready; m_s readers done

        // ---- stats update (designated lanes) ----
        if (wn == 0 && tig == 0) {
            #pragma unroll
            for (int mf = 0; mf < 2; mf++)
                #pragma unroll
                for (int hh = 0; hh < 2; hh++) {
                    const int r = wm * 32 + mf * 16 + gid + 8 * hh;
                    m_s[r] = mnew[mf][hh];
                    l_s[r] = alph[mf][hh] * l_s[r] + wsum[r] + wsum[128 + r];
                }
        }

        // ---- O += P V (3-term split) ----
        #pragma unroll
        for (int k = 0; k < 8; k++) {
            unsigned ph4[4], pl4[4];
            unsigned po = (unsigned)((wid * 16 + a_row) * 272 + (k * 16 + a_col) * 2);
            ldsm4(ph4, sb + PH_OFF + po);
            ldsm4(pl4, sb + PL_OFF + po);
            #pragma unroll
            for (int ng = 0; ng < 8; ng++) {
                unsigned vo = (unsigned)((k * 16 + v_key) * 272 + (ng * 16 + v_ecol) * 2);
                unsigned vh4[4], vl4[4];
                ldsm4t(vh4, sb + KH_OFF + vo);
                ldsm4t(vl4, sb + KL_OFF + vo);
                mma16816(o[2*ng],   ph4, vh4[0], vh4[1]);
                mma16816(o[2*ng],   ph4, vl4[0], vl4[1]);
                mma16816(o[2*ng],   pl4, vh4[0], vh4[1]);
                mma16816(o[2*ng+1], ph4, vh4[2], vh4[3]);
                mma16816(o[2*ng+1], ph4, vl4[2], vl4[3]);
                mma16816(o[2*ng+1], pl4, vh4[2], vh4[3]);
            }
        }
        __syncthreads();   // PV done; stats visible for next chunk
    }

    // ---- normalize and store ----
    const int ro0 = wid * 16 + gid;
    const float li0 = 1.f / l_s[ro0];
    const float li1 = 1.f / l_s[ro0 + 8];
    float* Y = g_y + ((size_t)bh * N_ + q0) * E_;
    #pragma unroll
    for (int nf = 0; nf < 16; nf++) {
        const int e = nf * 8 + 2 * tig;
        *(float2*)&Y[(size_t)ro0 * E_ + e]       = make_float2(o[nf][0] * li0, o[nf][1] * li0);
        *(float2*)&Y[(size_t)(ro0 + 8) * E_ + e] = make_float2(o[nf][2] * li1, o[nf][3] * li1);
    }
}

// ---------------------------------------------------------------------------
// Kernel 3: out = Y @ Wo^T + bo, * mask (fp32 SIMT)
// ---------------------------------------------------------------------------
__global__ __launch_bounds__(256) void oproj_kernel(
    const float* __restrict__ Wo, const float* __restrict__ bo,
    const float* __restrict__ mask, float* __restrict__ out)
{
    __shared__ float as_[64][68];
    __shared__ float ws_[64][68];

    const int tid  = threadIdx.x;
    const int ty   = tid >> 4;
    const int tx   = tid & 15;
    const int row0 = blockIdx.x << 6;
    const int col0 = blockIdx.y << 6;

    float acc[4][4] = {};

    for (int k0 = 0; k0 < 1024; k0 += 64) {
        const int h = k0 >> 7;
        const int eoff = k0 & 127;
        #pragma unroll
        for (int i = 0; i < 16; i++) {
            int idx = tid + (i << 8);
            int r = idx >> 6, kk = idx & 63;
            int rw = row0 + r;
            int b = rw >> 9, n = rw & 511;
            as_[kk][r] = g_y[((size_t)((b * H_ + h) * N_ + n) << 7) + eoff + kk];
        }
        #pragma unroll
        for (int i = 0; i < 16; i++) {
            int idx = tid + (i << 8);
            int c = idx >> 6, kk = idx & 63;
            ws_[kk][c] = Wo[(col0 + c) * 1024 + k0 + kk];
        }
        __syncthreads();
        #pragma unroll 8
        for (int kk = 0; kk < 64; kk++) {
            float4 av = *(const float4*)&as_[kk][ty << 2];
            float4 wv = *(const float4*)&ws_[kk][tx << 2];
            float a[4] = {av.x, av.y, av.z, av.w};
            float w[4] = {wv.x, wv.y, wv.z, wv.w};
            #pragma unroll
            for (int i = 0; i < 4; i++)
                #pragma unroll
                for (int j = 0; j < 4; j++)
                    acc[i][j] += a[i] * w[j];
        }
        __syncthreads();
    }

    float4 bv4 = *(const float4*)&bo[col0 + (tx << 2)];
    #pragma unroll
    for (int i = 0; i < 4; i++) {
        int rw = row0 + (ty << 2) + i;
        int b = rw >> 9, n = rw & 511;
        float mv = mask[b * 512 + n];
        float4 o = make_float4((acc[i][0] + bv4.x) * mv, (acc[i][1] + bv4.y) * mv,
                               (acc[i][2] + bv4.z) * mv, (acc[i][3] + bv4.w) * mv);
        *(float4*)&out[(size_t)rw * E_ + col0 + (tx << 2)] = o;
    }
}

// ---------------------------------------------------------------------------
extern "C" void kernel_launch(void* const* d_in, const int* in_sizes, int n_in,
                              void* d_out, int out_size)
{
    const float* x    = (const float*)d_in[0];
    const float* dist = (const float*)d_in[1];
    const float* mask = (const float*)d_in[2];
    const float* Wq   = (const float*)d_in[3];
    const float* bq   = (const float*)d_in[4];
    const float* Wk   = (const float*)d_in[5];
    const float* bk   = (const float*)d_in[6];
    const float* Wv   = (const float*)d_in[7];
    const float* bv   = (const float*)d_in[8];
    const float* Wo   = (const float*)d_in[9];
    const float* bo   = (const float*)d_in[10];
    float* out = (float*)d_out;

    cudaFuncSetAttribute(attn_mma_kernel,
                         cudaFuncAttributeMaxDynamicSharedMemorySize,
                         SMEM_ATTN);

    qkv_kernel<<<dim3(128, 16, 3), 256>>>(x, Wq, bq, Wk, bk, Wv, bv);
    attn_mma_kernel<<<dim3(4, 128), 256, SMEM_ATTN>>>(dist, mask);
    oproj_kernel<<<dim3(128, 2), 256>>>(Wo, bo, mask, out);
}

// round 5
// speedup vs baseline: 2.9542x; 1.5878x over previous
#include <cuda_runtime.h>
#include <cuda_bf16.h>
#include <math.h>

#define B_ 16
#define N_ 512
#define H_ 8
#define E_ 128
#define BH_ (B_*H_)
#define NEGV (-1000000000.0f)
#define SCALE_ 0.08838834764831845f

// Intermediates in device globals (no runtime allocation allowed).
__device__ float g_q[BH_*N_*E_];
__device__ float g_k[BH_*N_*E_];
__device__ float g_v[BH_*N_*E_];
__device__ float g_y[BH_*N_*E_];

// ---------------------------------------------------------------------------
// mma.sync / ldmatrix helpers (base PTX, sm_80+, works on target sm_103)
// ---------------------------------------------------------------------------
__device__ __forceinline__ unsigned smem_u32(const void* p) {
    unsigned r;
    asm("{ .reg .u64 t; cvta.to.shared.u64 t, %1; cvt.u32.u64 %0, t; }" : "=r"(r) : "l"(p));
    return r;
}
__device__ __forceinline__ void ldsm4(unsigned r[4], unsigned addr) {
    asm volatile("ldmatrix.sync.aligned.m8n8.x4.shared.b16 {%0,%1,%2,%3}, [%4];"
        : "=r"(r[0]), "=r"(r[1]), "=r"(r[2]), "=r"(r[3]) : "r"(addr));
}
__device__ __forceinline__ void ldsm4t(unsigned r[4], unsigned addr) {
    asm volatile("ldmatrix.sync.aligned.m8n8.x4.trans.shared.b16 {%0,%1,%2,%3}, [%4];"
        : "=r"(r[0]), "=r"(r[1]), "=r"(r[2]), "=r"(r[3]) : "r"(addr));
}
__device__ __forceinline__ void mma16816(float c[4], const unsigned a[4],
                                         unsigned b0, unsigned b1) {
    asm volatile("mma.sync.aligned.m16n8k16.row.col.f32.bf16.bf16.f32 "
        "{%0,%1,%2,%3}, {%4,%5,%6,%7}, {%8,%9}, {%0,%1,%2,%3};"
        : "+f"(c[0]), "+f"(c[1]), "+f"(c[2]), "+f"(c[3])
        : "r"(a[0]), "r"(a[1]), "r"(a[2]), "r"(a[3]), "r"(b0), "r"(b1));
}

// load `rows` x 128 fp32 tile (row stride `stride` floats), scale, split to
// bf16 hi/lo into smem (272-byte row stride). 256 threads.
__device__ __forceinline__ void load_split(const float* __restrict__ src,
        size_t stride, char* smc, int offH, int offL, float scale, int rows, int tid)
{
    const int iters = rows >> 3;     // rows*32 float4 / 256 threads
    for (int i = 0; i < iters; i++) {
        int idx = tid + (i << 8);
        int r = idx >> 5, c4 = idx & 31;
        float4 v = *(const float4*)(src + (size_t)r * stride + c4 * 4);
        float x0 = v.x * scale, x1 = v.y * scale, x2 = v.z * scale, x3 = v.w * scale;
        __nv_bfloat162 h01 = __floats2bfloat162_rn(x0, x1);
        __nv_bfloat162 h23 = __floats2bfloat162_rn(x2, x3);
        __nv_bfloat162 l01 = __floats2bfloat162_rn(
            x0 - __bfloat162float(__low2bfloat16(h01)),
            x1 - __bfloat162float(__high2bfloat16(h01)));
        __nv_bfloat162 l23 = __floats2bfloat162_rn(
            x2 - __bfloat162float(__low2bfloat16(h23)),
            x3 - __bfloat162float(__high2bfloat16(h23)));
        *(uint2*)(smc + offH + r * 272 + c4 * 8) = make_uint2(*(unsigned*)&h01, *(unsigned*)&h23);
        *(uint2*)(smc + offL + r * 272 + c4 * 8) = make_uint2(*(unsigned*)&l01, *(unsigned*)&l23);
    }
}

// ---------------------------------------------------------------------------
// Kernel 1: QKV projection on mma.sync (split-bf16 3-term).
// C[8192,1024] = X @ W^T + b for q/k/v. 128x128 tile per CTA, 8 warps.
// ---------------------------------------------------------------------------
#define QG_XH 0
#define QG_XL 34816
#define QG_WH 69632
#define QG_WL 104448
#define SMEM_QKV 139264

__global__ __launch_bounds__(256, 1) void qkv_mma_kernel(
    const float* __restrict__ x,
    const float* __restrict__ Wq, const float* __restrict__ bq,
    const float* __restrict__ Wk, const float* __restrict__ bk,
    const float* __restrict__ Wv, const float* __restrict__ bv)
{
    extern __shared__ char smc[];
    const unsigned sb = smem_u32(smc);

    const int which = blockIdx.z;
    const float* __restrict__ W    = (which == 0) ? Wq : (which == 1) ? Wk : Wv;
    const float* __restrict__ bias = (which == 0) ? bq : (which == 1) ? bk : bv;
    float* __restrict__ out        = (which == 0) ? g_q : (which == 1) ? g_k : g_v;

    const int tid  = threadIdx.x;
    const int lane = tid & 31;
    const int wid  = tid >> 5;
    const int wm   = wid >> 1;
    const int wn   = wid & 1;
    const int gid  = lane >> 2;
    const int tig  = lane & 3;

    const int row0 = blockIdx.x << 7;
    const int col0 = blockIdx.y << 7;

    const int a_row = (lane & 15);
    const int a_col = ((lane >> 4) << 3);
    const int b_key = (lane & 7) + ((lane >> 4) << 3);
    const int b_ecol = (((lane >> 3) & 1) << 3);

    load_split(x + (size_t)row0 * E_, E_, smc, QG_XH, QG_XL, 1.0f, 128, tid);
    load_split(W + (size_t)col0 * E_, E_, smc, QG_WH, QG_WL, 1.0f, 128, tid);
    __syncthreads();

    float acc[2][8][4] = {};
    #pragma unroll
    for (int k = 0; k < 8; k++) {
        unsigned ah[2][4], al[2][4];
        #pragma unroll
        for (int mf = 0; mf < 2; mf++) {
            unsigned ao = (unsigned)((wm * 32 + mf * 16 + a_row) * 272 + (k * 16 + a_col) * 2);
            ldsm4(ah[mf], sb + QG_XH + ao);
            ldsm4(al[mf], sb + QG_XL + ao);
        }
        #pragma unroll
        for (int ng = 0; ng < 4; ng++) {
            unsigned bo = (unsigned)((wn * 64 + ng * 16 + b_key) * 272 + (k * 16 + b_ecol) * 2);
            unsigned bh4[4], bl4[4];
            ldsm4(bh4, sb + QG_WH + bo);
            ldsm4(bl4, sb + QG_WL + bo);
            #pragma unroll
            for (int mf = 0; mf < 2; mf++) {
                mma16816(acc[mf][2*ng],   ah[mf], bh4[0], bh4[1]);
                mma16816(acc[mf][2*ng],   ah[mf], bl4[0], bl4[1]);
                mma16816(acc[mf][2*ng],   al[mf], bh4[0], bh4[1]);
                mma16816(acc[mf][2*ng+1], ah[mf], bh4[2], bh4[3]);
                mma16816(acc[mf][2*ng+1], ah[mf], bl4[2], bl4[3]);
                mma16816(acc[mf][2*ng+1], al[mf], bh4[2], bh4[3]);
            }
        }
    }

    // epilogue: + bias, store fp32 to [b,h,n,e] layout
    const int hh = col0 >> 7;
    #pragma unroll
    for (int mf = 0; mf < 2; mf++) {
        const int lr0 = wm * 32 + mf * 16 + gid;
        #pragma unroll
        for (int nf = 0; nf < 8; nf++) {
            const int cb = wn * 64 + nf * 8 + 2 * tig;
            const float b0v = bias[col0 + cb], b1v = bias[col0 + cb + 1];
            int rw = row0 + lr0;
            int b = rw >> 9, n = rw & 511;
            *(float2*)&out[((size_t)((b * H_ + hh) * N_ + n) << 7) + cb] =
                make_float2(acc[mf][nf][0] + b0v, acc[mf][nf][1] + b1v);
            rw += 8; n = rw & 511; b = rw >> 9;
            *(float2*)&out[((size_t)((b * H_ + hh) * N_ + n) << 7) + cb] =
                make_float2(acc[mf][nf][2] + b0v, acc[mf][nf][3] + b1v);
        }
    }
}

// ---------------------------------------------------------------------------
// Kernel 2: flash-style attention on mma.sync (unchanged from R4 — passing)
// ---------------------------------------------------------------------------
#define QH_OFF   0
#define QL_OFF   34816
#define KH_OFF   69632
#define KL_OFF   104448
#define PH_OFF   139264
#define PL_OFF   174080
#define MK_OFF   208896
#define MS_OFF   210944
#define LS_OFF   211456
#define WMAX_OFF 211968
#define WSUM_OFF 212992
#define SMEM_ATTN 214016

__global__ __launch_bounds__(256, 1) void attn_mma_kernel(
    const float* __restrict__ dist, const float* __restrict__ mask)
{
    extern __shared__ char smc[];
    const unsigned sb = smem_u32(smc);
    float* mk   = (float*)(smc + MK_OFF);
    float* m_s  = (float*)(smc + MS_OFF);
    float* l_s  = (float*)(smc + LS_OFF);
    float* wmax = (float*)(smc + WMAX_OFF);
    float* wsum = (float*)(smc + WSUM_OFF);

    const int tid  = threadIdx.x;
    const int lane = tid & 31;
    const int wid  = tid >> 5;
    const int wm   = wid >> 1;
    const int wn   = wid & 1;
    const int gid  = lane >> 2;
    const int tig  = lane & 3;

    const int q0 = blockIdx.x << 7;
    const int bh = blockIdx.y;
    const int b  = bh >> 3;

    for (int i = tid; i < 512; i += 256) mk[i] = mask[b * 512 + i];
    if (tid < 128) { m_s[tid] = -3.0e38f; l_s[tid] = 0.f; }

    load_split(g_q + ((size_t)bh * N_ + q0) * E_, E_, smc, QH_OFF, QL_OFF, SCALE_, 128, tid);

    float o[16][4] = {};

    const int a_row = (lane & 15);
    const int a_col = ((lane >> 4) << 3);
    const int b_key = (lane & 7) + ((lane >> 4) << 3);
    const int b_ecol = (((lane >> 3) & 1) << 3);
    const int v_key = (lane & 7) + (((lane >> 3) & 1) << 3);
    const int v_ecol = ((lane >> 4) << 3);

    for (int kt = 0; kt < 4; kt++) {
        load_split(g_k + ((size_t)bh * N_ + kt * 128) * E_, E_, smc, KH_OFF, KL_OFF, 1.0f, 128, tid);
        __syncthreads();

        float acc[2][8][4] = {};
        #pragma unroll
        for (int k = 0; k < 8; k++) {
            unsigned ah[2][4], al[2][4];
            #pragma unroll
            for (int mf = 0; mf < 2; mf++) {
                unsigned ao = (unsigned)((wm * 32 + mf * 16 + a_row) * 272 + (k * 16 + a_col) * 2);
                ldsm4(ah[mf], sb + QH_OFF + ao);
                ldsm4(al[mf], sb + QL_OFF + ao);
            }
            #pragma unroll
            for (int ng = 0; ng < 4; ng++) {
                unsigned bo = (unsigned)((wn * 64 + ng * 16 + b_key) * 272 + (k * 16 + b_ecol) * 2);
                unsigned bh4[4], bl4[4];
                ldsm4(bh4, sb + KH_OFF + bo);
                ldsm4(bl4, sb + KL_OFF + bo);
                #pragma unroll
                for (int mf = 0; mf < 2; mf++) {
                    mma16816(acc[mf][2*ng],   ah[mf], bh4[0], bh4[1]);
                    mma16816(acc[mf][2*ng],   ah[mf], bl4[0], bl4[1]);
                    mma16816(acc[mf][2*ng],   al[mf], bh4[0], bh4[1]);
                    mma16816(acc[mf][2*ng+1], ah[mf], bh4[2], bh4[3]);
                    mma16816(acc[mf][2*ng+1], ah[mf], bl4[2], bl4[3]);
                    mma16816(acc[mf][2*ng+1], al[mf], bh4[2], bh4[3]);
                }
            }
        }

        float mx[2][2] = {{-3.0e38f, -3.0e38f}, {-3.0e38f, -3.0e38f}};
        #pragma unroll
        for (int mf = 0; mf < 2; mf++) {
            const int lr0 = wm * 32 + mf * 16 + gid;
            #pragma unroll
            for (int nf = 0; nf < 8; nf++) {
                const int cb = wn * 64 + nf * 8 + 2 * tig;
                const int gcol = kt * 128 + cb;
                const float* dp = dist + ((size_t)b * N_ + q0 + lr0) * N_ + gcol;
                float2 d0 = *(const float2*)dp;
                float2 d1 = *(const float2*)(dp + 8 * N_);
                const bool k0 = (mk[gcol] != 0.f), k1 = (mk[gcol + 1] != 0.f);
                float s0 = k0 ? acc[mf][nf][0] + d0.x : NEGV;
                float s1 = k1 ? acc[mf][nf][1] + d0.y : NEGV;
                float s2 = k0 ? acc[mf][nf][2] + d1.x : NEGV;
                float s3 = k1 ? acc[mf][nf][3] + d1.y : NEGV;
                acc[mf][nf][0] = s0; acc[mf][nf][1] = s1;
                acc[mf][nf][2] = s2; acc[mf][nf][3] = s3;
                mx[mf][0] = fmaxf(mx[mf][0], fmaxf(s0, s1));
                mx[mf][1] = fmaxf(mx[mf][1], fmaxf(s2, s3));
            }
        }
        #pragma unroll
        for (int mf = 0; mf < 2; mf++)
            #pragma unroll
            for (int hh = 0; hh < 2; hh++) {
                float m = mx[mf][hh];
                m = fmaxf(m, __shfl_xor_sync(0xffffffffu, m, 1));
                m = fmaxf(m, __shfl_xor_sync(0xffffffffu, m, 2));
                mx[mf][hh] = m;
            }
        if (tig == 0) {
            #pragma unroll
            for (int mf = 0; mf < 2; mf++)
                #pragma unroll
                for (int hh = 0; hh < 2; hh++)
                    wmax[wn * 128 + wm * 32 + mf * 16 + gid + 8 * hh] = mx[mf][hh];
        }
        __syncthreads();

        load_split(g_v + ((size_t)bh * N_ + kt * 128) * E_, E_, smc, KH_OFF, KL_OFF, 1.0f, 128, tid);

        float mnew[2][2], alph[2][2], rs[2][2] = {};
        #pragma unroll
        for (int mf = 0; mf < 2; mf++)
            #pragma unroll
            for (int hh = 0; hh < 2; hh++) {
                const int r = wm * 32 + mf * 16 + gid + 8 * hh;
                const float mo = m_s[r];
                const float mn = fmaxf(fmaxf(wmax[r], wmax[128 + r]), mo);
                mnew[mf][hh] = mn;
                alph[mf][hh] = __expf(mo - mn);
            }
        #pragma unroll
        for (int mf = 0; mf < 2; mf++) {
            const int lr0 = wm * 32 + mf * 16 + gid;
            #pragma unroll
            for (int nf = 0; nf < 8; nf++) {
                const int cb = wn * 64 + nf * 8 + 2 * tig;
                float p0 = __expf(acc[mf][nf][0] - mnew[mf][0]);
                float p1 = __expf(acc[mf][nf][1] - mnew[mf][0]);
                float p2 = __expf(acc[mf][nf][2] - mnew[mf][1]);
                float p3 = __expf(acc[mf][nf][3] - mnew[mf][1]);
                rs[mf][0] += p0 + p1;
                rs[mf][1] += p2 + p3;
                __nv_bfloat162 hA = __floats2bfloat162_rn(p0, p1);
                __nv_bfloat162 lA = __floats2bfloat162_rn(
                    p0 - __bfloat162float(__low2bfloat16(hA)),
                    p1 - __bfloat162float(__high2bfloat16(hA)));
                __nv_bfloat162 hB = __floats2bfloat162_rn(p2, p3);
                __nv_bfloat162 lB = __floats2bfloat162_rn(
                    p2 - __bfloat162float(__low2bfloat16(hB)),
                    p3 - __bfloat162float(__high2bfloat16(hB)));
                *(unsigned*)(smc + PH_OFF + lr0 * 272 + cb * 2)       = *(unsigned*)&hA;
                *(unsigned*)(smc + PL_OFF + lr0 * 272 + cb * 2)       = *(unsigned*)&lA;
                *(unsigned*)(smc + PH_OFF + (lr0 + 8) * 272 + cb * 2) = *(unsigned*)&hB;
                *(unsigned*)(smc + PL_OFF + (lr0 + 8) * 272 + cb * 2) = *(unsigned*)&lB;
            }
        }
        #pragma unroll
        for (int mf = 0; mf < 2; mf++)
            #pragma unroll
            for (int hh = 0; hh < 2; hh++) {
                float s = rs[mf][hh];
                s += __shfl_xor_sync(0xffffffffu, s, 1);
                s += __shfl_xor_sync(0xffffffffu, s, 2);
                rs[mf][hh] = s;
            }
        if (tig == 0) {
            #pragma unroll
            for (int mf = 0; mf < 2; mf++)
                #pragma unroll
                for (int hh = 0; hh < 2; hh++)
                    wsum[wn * 128 + wm * 32 + mf * 16 + gid + 8 * hh] = rs[mf][hh];
        }
        {
            const int ro0 = wid * 16 + gid;
            const float mo0 = m_s[ro0];
            const float a0 = __expf(mo0 - fmaxf(fmaxf(wmax[ro0], wmax[128 + ro0]), mo0));
            const int ro1 = ro0 + 8;
            const float mo1 = m_s[ro1];
            const float a1 = __expf(mo1 - fmaxf(fmaxf(wmax[ro1], wmax[128 + ro1]), mo1));
            #pragma unroll
            for (int nf = 0; nf < 16; nf++) {
                o[nf][0] *= a0; o[nf][1] *= a0;
                o[nf][2] *= a1; o[nf][3] *= a1;
            }
        }
        __syncthreads();

        if (wn == 0 && tig == 0) {
            #pragma unroll
            for (int mf = 0; mf < 2; mf++)
                #pragma unroll
                for (int hh = 0; hh < 2; hh++) {
                    const int r = wm * 32 + mf * 16 + gid + 8 * hh;
                    m_s[r] = mnew[mf][hh];
                    l_s[r] = alph[mf][hh] * l_s[r] + wsum[r] + wsum[128 + r];
                }
        }

        #pragma unroll
        for (int k = 0; k < 8; k++) {
            unsigned ph4[4], pl4[4];
            unsigned po = (unsigned)((wid * 16 + a_row) * 272 + (k * 16 + a_col) * 2);
            ldsm4(ph4, sb + PH_OFF + po);
            ldsm4(pl4, sb + PL_OFF + po);
            #pragma unroll
            for (int ng = 0; ng < 8; ng++) {
                unsigned vo = (unsigned)((k * 16 + v_key) * 272 + (ng * 16 + v_ecol) * 2);
                unsigned vh4[4], vl4[4];
                ldsm4t(vh4, sb + KH_OFF + vo);
                ldsm4t(vl4, sb + KL_OFF + vo);
                mma16816(o[2*ng],   ph4, vh4[0], vh4[1]);
                mma16816(o[2*ng],   ph4, vl4[0], vl4[1]);
                mma16816(o[2*ng],   pl4, vh4[0], vh4[1]);
                mma16816(o[2*ng+1], ph4, vh4[2], vh4[3]);
                mma16816(o[2*ng+1], ph4, vl4[2], vl4[3]);
                mma16816(o[2*ng+1], pl4, vh4[2], vh4[3]);
            }
        }
        __syncthreads();
    }

    const int ro0 = wid * 16 + gid;
    const float li0 = 1.f / l_s[ro0];
    const float li1 = 1.f / l_s[ro0 + 8];
    float* Y = g_y + ((size_t)bh * N_ + q0) * E_;
    #pragma unroll
    for (int nf = 0; nf < 16; nf++) {
        const int e = nf * 8 + 2 * tig;
        *(float2*)&Y[(size_t)ro0 * E_ + e]       = make_float2(o[nf][0] * li0, o[nf][1] * li0);
        *(float2*)&Y[(size_t)(ro0 + 8) * E_ + e] = make_float2(o[nf][2] * li1, o[nf][3] * li1);
    }
}

// ---------------------------------------------------------------------------
// Kernel 3: out = Y @ Wo^T + bo, * mask  on mma.sync (split-bf16 3-term).
// 64x128 tile per CTA, K=1024 in 8 head-chunks. grid(128).
// ---------------------------------------------------------------------------
#define OG_AH 0
#define OG_AL 17408
#define OG_BH 34816
#define OG_BL 69632
#define SMEM_OPROJ 104448

__global__ __launch_bounds__(256, 1) void oproj_mma_kernel(
    const float* __restrict__ Wo, const float* __restrict__ bo,
    const float* __restrict__ mask, float* __restrict__ out)
{
    extern __shared__ char smc[];
    const unsigned sb = smem_u32(smc);

    const int tid  = threadIdx.x;
    const int lane = tid & 31;
    const int wid  = tid >> 5;
    const int wm   = wid >> 1;
    const int wn   = wid & 1;
    const int gid  = lane >> 2;
    const int tig  = lane & 3;

    const int row0 = blockIdx.x << 6;            // 128 blocks of 64 rows
    const int b    = row0 >> 9;
    const int n0   = row0 & 511;

    const int a_row = (lane & 15);
    const int a_col = ((lane >> 4) << 3);
    const int b_key = (lane & 7) + ((lane >> 4) << 3);
    const int b_ecol = (((lane >> 3) & 1) << 3);

    float acc[8][4] = {};

    for (int h = 0; h < 8; h++) {
        load_split(g_y + ((size_t)(b * H_ + h) * N_ + n0) * E_, E_,
                   smc, OG_AH, OG_AL, 1.0f, 64, tid);
        load_split(Wo + (size_t)h * 128, 1024, smc, OG_BH, OG_BL, 1.0f, 128, tid);
        __syncthreads();

        #pragma unroll
        for (int k = 0; k < 8; k++) {
            unsigned ah[4], al[4];
            unsigned ao = (unsigned)((wm * 16 + a_row) * 272 + (k * 16 + a_col) * 2);
            ldsm4(ah, sb + OG_AH + ao);
            ldsm4(al, sb + OG_AL + ao);
            #pragma unroll
            for (int ng = 0; ng < 4; ng++) {
                unsigned bo_ = (unsigned)((wn * 64 + ng * 16 + b_key) * 272 + (k * 16 + b_ecol) * 2);
                unsigned bh4[4], bl4[4];
                ldsm4(bh4, sb + OG_BH + bo_);
                ldsm4(bl4, sb + OG_BL + bo_);
                mma16816(acc[2*ng],   ah, bh4[0], bh4[1]);
                mma16816(acc[2*ng],   ah, bl4[0], bl4[1]);
                mma16816(acc[2*ng],   al, bh4[0], bh4[1]);
                mma16816(acc[2*ng+1], ah, bh4[2], bh4[3]);
                mma16816(acc[2*ng+1], ah, bl4[2], bl4[3]);
                mma16816(acc[2*ng+1], al, bh4[2], bh4[3]);
            }
        }
        __syncthreads();
    }

    // epilogue: + bias, * query mask
    const int lr0 = wm * 16 + gid;
    const int rw0 = row0 + lr0;
    const float mv0 = mask[b * 512 + (rw0 & 511)];
    const float mv1 = mask[b * 512 + ((rw0 + 8) & 511)];
    #pragma unroll
    for (int nf = 0; nf < 8; nf++) {
        const int cb = wn * 64 + nf * 8 + 2 * tig;
        const float b0v = bo[cb], b1v = bo[cb + 1];
        *(float2*)&out[(size_t)rw0 * E_ + cb] =
            make_float2((acc[nf][0] + b0v) * mv0, (acc[nf][1] + b1v) * mv0);
        *(float2*)&out[(size_t)(rw0 + 8) * E_ + cb] =
            make_float2((acc[nf][2] + b0v) * mv1, (acc[nf][3] + b1v) * mv1);
    }
}

// ---------------------------------------------------------------------------
extern "C" void kernel_launch(void* const* d_in, const int* in_sizes, int n_in,
                              void* d_out, int out_size)
{
    const float* x    = (const float*)d_in[0];
    const float* dist = (const float*)d_in[1];
    const float* mask = (const float*)d_in[2];
    const float* Wq   = (const float*)d_in[3];
    const float* bq   = (const float*)d_in[4];
    const float* Wk   = (const float*)d_in[5];
    const float* bk   = (const float*)d_in[6];
    const float* Wv   = (const float*)d_in[7];
    const float* bv   = (const float*)d_in[8];
    const float* Wo   = (const float*)d_in[9];
    const float* bo   = (const float*)d_in[10];
    float* out = (float*)d_out;

    cudaFuncSetAttribute(qkv_mma_kernel,
                         cudaFuncAttributeMaxDynamicSharedMemorySize, SMEM_QKV);
    cudaFuncSetAttribute(attn_mma_kernel,
                         cudaFuncAttributeMaxDynamicSharedMemorySize, SMEM_ATTN);
    cudaFuncSetAttribute(oproj_mma_kernel,
                         cudaFuncAttributeMaxDynamicSharedMemorySize, SMEM_OPROJ);

    qkv_mma_kernel<<<dim3(64, 8, 3), 256, SMEM_QKV>>>(x, Wq, bq, Wk, bk, Wv, bv);
    attn_mma_kernel<<<dim3(4, 128), 256, SMEM_ATTN>>>(dist, mask);
    oproj_mma_kernel<<<128, 256, SMEM_OPROJ>>>(Wo, bo, mask, out);
}